// round 2
// baseline (speedup 1.0000x reference)
#include <cuda_runtime.h>
#include <cuda_bf16.h>
#include <math.h>

// DistanceTransformLoss fused kernel for (32,1,1024,1024) fp32 inputs.
//
// dist[h] = min(H, distance to nearest target==1 in the same (n,w) column).
// penalty = (pred>0) * dist ; border = total/max(count,1) (0 if total==0)
// out = mean(BCEWithLogits) + sqrt(border)
//
// Strategy: one pass over HBM. Each thread owns 128 rows of one column,
// bit-packs targets and sign(pred) into 4x u32 masks, computes BCE on the
// fly, then resolves nearest-one distances with clz/ffs + tiny smem carry
// exchange (8 segments per column, one block per 1024x32 column tile).

#define HH 1024
#define WW 1024
#define NEGP (-(1 << 29))
#define BIGP ((1 << 29))

__device__ unsigned long long g_total;
__device__ unsigned int g_count;
__device__ double g_bce;

__global__ void init_kernel() {
    g_total = 0ull;
    g_count = 0u;
    g_bce = 0.0;
}

__global__ __launch_bounds__(256) void dtl_main(const float* __restrict__ pred,
                                                const float* __restrict__ targ) {
    const int tx = threadIdx.x;          // column within tile (0..31)
    const int ty = threadIdx.y;          // H-segment (0..7), 128 rows each
    const int n  = blockIdx.y;
    const int w0 = blockIdx.x * 32;
    const size_t base = (size_t)n * (HH * WW) + (w0 + tx);
    const int hbase = ty * 128;

    unsigned tbits[4], pbits[4];
    float bce = 0.0f;

    // ---- load + binarize + BCE ----
    #pragma unroll
    for (int wd = 0; wd < 4; ++wd) {
        unsigned tb = 0u, pb = 0u;
        const int h0 = hbase + wd * 32;
        #pragma unroll 8
        for (int r = 0; r < 32; ++r) {
            const size_t idx = base + (size_t)(h0 + r) * WW;
            const float t = targ[idx];
            const float p = pred[idx];
            tb |= (t > 0.5f ? 1u : 0u) << r;
            pb |= (p > 0.0f ? 1u : 0u) << r;
            const float ap = fabsf(p);
            bce += fmaxf(p, 0.0f) - p * t + __logf(1.0f + __expf(-ap));
        }
        tbits[wd] = tb;
        pbits[wd] = pb;
    }

    // ---- per-segment summary: first/last set-bit global row ----
    int last_in = NEGP;
    int first_in = BIGP;
    #pragma unroll
    for (int wd = 0; wd < 4; ++wd) {
        if (tbits[wd]) {
            last_in = hbase + wd * 32 + (31 - __clz(tbits[wd]));
            if (first_in == BIGP)
                first_in = hbase + wd * 32 + (__ffs(tbits[wd]) - 1);
        }
    }

    __shared__ int s_last[8][32];
    __shared__ int s_first[8][32];
    s_last[ty][tx] = last_in;
    s_first[ty][tx] = first_in;
    __syncthreads();

    // carry-in from other segments of this column
    int p_seg = NEGP;
    for (int s = 0; s < ty; ++s) {
        const int v = s_last[s][tx];
        p_seg = v > p_seg ? v : p_seg;
    }
    int n_seg = BIGP;
    for (int s = ty + 1; s < 8; ++s) {
        const int v = s_first[s][tx];
        n_seg = v < n_seg ? v : n_seg;
    }

    // per-word carries inside the segment
    int p_w[4], n_w[4];
    p_w[0] = p_seg;
    #pragma unroll
    for (int wd = 1; wd < 4; ++wd)
        p_w[wd] = tbits[wd - 1]
                    ? (hbase + (wd - 1) * 32 + 31 - __clz(tbits[wd - 1]))
                    : p_w[wd - 1];
    n_w[3] = n_seg;
    #pragma unroll
    for (int wd = 2; wd >= 0; --wd)
        n_w[wd] = tbits[wd + 1]
                    ? (hbase + (wd + 1) * 32 + __ffs(tbits[wd + 1]) - 1)
                    : n_w[wd + 1];

    // ---- per-row distance + penalty accumulation ----
    unsigned tot = 0u, cnt = 0u;
    #pragma unroll
    for (int wd = 0; wd < 4; ++wd) {
        const unsigned tb = tbits[wd];
        const unsigned pb = pbits[wd];
        const int h0 = hbase + wd * 32;
        #pragma unroll 8
        for (int r = 0; r < 32; ++r) {
            const unsigned tlo = tb << (31 - r);   // bits at rows <= r
            const unsigned thi = tb >> r;          // bits at rows >= r
            const int h = h0 + r;
            int na = tlo ? __clz(tlo) : (h - p_w[wd]);
            int nb = thi ? (__ffs(thi) - 1) : (n_w[wd] - h);
            int d = na < nb ? na : nb;
            d = d < 1024 ? d : 1024;
            const unsigned pbit = (pb >> r) & 1u;
            tot += pbit ? (unsigned)d : 0u;
            cnt += (pbit & (d > 0 ? 1u : 0u));
        }
    }

    // ---- block reduction ----
    #pragma unroll
    for (int off = 16; off > 0; off >>= 1) {
        tot += __shfl_down_sync(0xFFFFFFFFu, tot, off);
        cnt += __shfl_down_sync(0xFFFFFFFFu, cnt, off);
        bce += __shfl_down_sync(0xFFFFFFFFu, bce, off);
    }
    __shared__ unsigned r_tot[8];
    __shared__ unsigned r_cnt[8];
    __shared__ float r_bce[8];
    if (tx == 0) {
        r_tot[ty] = tot;
        r_cnt[ty] = cnt;
        r_bce[ty] = bce;
    }
    __syncthreads();
    if (ty == 0 && tx == 0) {
        unsigned bt = 0u, bc = 0u;
        float bb = 0.0f;
        #pragma unroll
        for (int s = 0; s < 8; ++s) {
            bt += r_tot[s];
            bc += r_cnt[s];
            bb += r_bce[s];
        }
        atomicAdd(&g_total, (unsigned long long)bt);
        atomicAdd(&g_count, bc);
        atomicAdd(&g_bce, (double)bb);
    }
}

__global__ void final_kernel(float* out) {
    const double inv_n = 1.0 / (double)(32ull * 1024ull * 1024ull);
    const double bce_mean = g_bce * inv_n;
    double border = 0.0;
    if (g_total != 0ull) {
        const unsigned c = g_count > 1u ? g_count : 1u;
        border = (double)g_total / (double)c;
    }
    out[0] = (float)(bce_mean + sqrt(border));
}

extern "C" void kernel_launch(void* const* d_in, const int* in_sizes, int n_in,
                              void* d_out, int out_size) {
    const float* pred = (const float*)d_in[0];
    const float* targ = (const float*)d_in[1];
    float* out = (float*)d_out;

    init_kernel<<<1, 1>>>();
    dim3 block(32, 8);
    dim3 grid(32, 32);   // 32 W-tiles x 32 batch
    dtl_main<<<grid, block>>>(pred, targ);
    final_kernel<<<1, 1>>>(out);
}